// round 1
// baseline (speedup 1.0000x reference)
#include <cuda_runtime.h>
#include <cstdint>

// BiasedFeatureDropout: out = x * mask * 1.25
// mask[i] = (threefry2x32_partitionable_bits(i) < T(channel))
// T = 858993664 for channels [0,32), 3435974144 otherwise.
//
// Reproduces JAX partitionable threefry:
//   keys (k1,k2) = (0,1)  [jax.random.key(1)]
//   per-element counter i (64-bit, hi=0): x = (hi + ks0, lo + ks1)
//   20 rounds, ks = [0, 1, 0x1BD11BDB]; output = out0 ^ out1.

static constexpr unsigned KS2 = 0x1BD11BDBu;          // 0 ^ 1 ^ 0x1BD11BDA
static constexpr unsigned HW   = 56u * 56u;           // 3136, divisible by 4
static constexpr unsigned THR_BIAS = 858993664u;      // keep=0.2f  -> (bits < T)
static constexpr unsigned THR_REG  = 3435974144u;     // keep=0.8f

__device__ __forceinline__ unsigned rotl32(unsigned v, int s) {
    return __funnelshift_l(v, v, s);
}

__device__ __forceinline__ unsigned threefry_bits(unsigned ctr) {
    // x0 = 0 + ks0(=0) = 0 ; x1 = ctr + ks1(=1)
    unsigned x0 = 0u;
    unsigned x1 = ctr + 1u;
#define TF_RND(r) { x0 += x1; x1 = rotl32(x1, (r)) ^ x0; }
    // group 0 (rot 13,15,26,6), inject ks[1], ks[2]+1
    TF_RND(13) TF_RND(15) TF_RND(26) TF_RND(6)
    x0 += 1u;   x1 += KS2 + 1u;
    // group 1 (rot 17,29,16,24), inject ks[2], ks[0]+2
    TF_RND(17) TF_RND(29) TF_RND(16) TF_RND(24)
    x0 += KS2;  x1 += 2u;
    // group 2, inject ks[0], ks[1]+3
    TF_RND(13) TF_RND(15) TF_RND(26) TF_RND(6)
    /* x0 += 0 */ x1 += 1u + 3u;
    // group 3, inject ks[1], ks[2]+4
    TF_RND(17) TF_RND(29) TF_RND(16) TF_RND(24)
    x0 += 1u;   x1 += KS2 + 4u;
    // group 4, inject ks[2], ks[0]+5
    TF_RND(13) TF_RND(15) TF_RND(26) TF_RND(6)
    x0 += KS2;  x1 += 5u;
#undef TF_RND
    return x0 ^ x1;
}

__global__ __launch_bounds__(256)
void biased_dropout_kernel(const float4* __restrict__ x,
                           float4* __restrict__ y,
                           unsigned n_vec) {
    unsigned t = blockIdx.x * blockDim.x + threadIdx.x;
    if (t >= n_vec) return;

    unsigned base = t * 4u;
    // channel = (elem_idx / (H*W)) % 256 ; HW divisible by 4 so all 4 elems share it
    unsigned ch = (base / HW) & 255u;
    unsigned thr = (ch < 32u) ? THR_BIAS : THR_REG;

    float4 v = x[t];

    unsigned b0 = threefry_bits(base + 0u);
    unsigned b1 = threefry_bits(base + 1u);
    unsigned b2 = threefry_bits(base + 2u);
    unsigned b3 = threefry_bits(base + 3u);

    float4 o;
    o.x = (b0 < thr) ? v.x * 1.25f : 0.0f;
    o.y = (b1 < thr) ? v.y * 1.25f : 0.0f;
    o.z = (b2 < thr) ? v.z * 1.25f : 0.0f;
    o.w = (b3 < thr) ? v.w * 1.25f : 0.0f;

    y[t] = o;
}

extern "C" void kernel_launch(void* const* d_in, const int* in_sizes, int n_in,
                              void* d_out, int out_size) {
    (void)n_in; (void)out_size;
    const float4* x = (const float4*)d_in[0];
    float4* y = (float4*)d_out;
    unsigned n = (unsigned)in_sizes[0];      // 51,380,224 elements
    unsigned n_vec = n / 4u;                 // exact (HW stride divisible by 4)
    unsigned blocks = (n_vec + 255u) / 256u;
    biased_dropout_kernel<<<blocks, 256>>>(x, y, n_vec);
}